// round 14
// baseline (speedup 1.0000x reference)
#include <cuda_runtime.h>
#include <cuda_bf16.h>
#include <math.h>

// ===========================================================================
// MS-SSIM 16x3x512x512 fp32, 5 levels.  (revert to round-12 pipeline +
// division-free tile loads)
// pool_all_kernel: ONE launch builds the whole 4-level pyramid (256 thr/blk);
//   block 0 zeroes the g_acc accumulators.
// ssim_all_kernel: ONE launch, all 5 levels (5520 blocks), 6 CTAs/SM.
//   Tile load is division-free (row loop, strength-reduced offsets).
//   Core: sum/diff transform, packed f32x2 FMA.
// final_kernel: fp32 log2/exp2 combine.
// ===========================================================================

#define OC  128           // output columns per block (== threads)
#define ORR 24            // output rows per block
#define IR  (ORR + 10)    // 34 input rows
#define ICW (OC + 10)     // 138 input cols

// Gaussian taps, sigma=1.5, ws=11
#define G0 0.00102838f
#define G1 0.00759876f
#define G2 0.03600077f
#define G3 0.10936069f
#define G4 0.21300553f
#define G5 0.26601172f

#define C1V 1.0e-4f
#define C2V 9.0e-4f

// Scratch for pooled pyramids
#define S1 (48u * 256u * 256u)
#define S2 (48u * 128u * 128u)
#define S3 (48u * 64u  * 64u)
#define S4 (48u * 32u  * 32u)
#define O1 0u
#define O2 (S1)
#define O3 (S1 + S2)
#define O4 (S1 + S2 + S3)
#define TOT (S1 + S2 + S3 + S4)

// per-level block counts (ORR=24: GY = ceil((H-10)/24))
#define NB0 4032   // 4 x 21 x 48   (H=512)
#define NB1 1056   // 2 x 11 x 48   (H=256)
#define NB2 240    // 1 x  5 x 48   (H=128)
#define NB3 144    // 1 x  3 x 48   (H=64)
#define NB4 48     // 1 x  1 x 48   (H=32)
#define NBALL (NB0 + NB1 + NB2 + NB3 + NB4)   // 5520

__device__ float g_p1[TOT];
__device__ float g_p2[TOT];
__device__ double g_acc[10];

// ---- f32x2 packed helpers -------------------------------------------------
typedef unsigned long long ull;
__device__ __forceinline__ ull pk2(float lo, float hi) {
    ull r;
    asm("mov.b64 %0, {%1, %2};" : "=l"(r) : "f"(lo), "f"(hi));
    return r;
}
__device__ __forceinline__ void upk2(ull v, float& lo, float& hi) {
    asm("mov.b64 {%0, %1}, %2;" : "=f"(lo), "=f"(hi) : "l"(v));
}
__device__ __forceinline__ ull fma2(ull a, ull b, ull c) {
    ull d;
    asm("fma.rn.f32x2 %0, %1, %2, %3;" : "=l"(d) : "l"(a), "l"(b), "l"(c));
    return d;
}
__device__ __forceinline__ ull mul2(ull a, ull b) {
    ull d;
    asm("mul.rn.f32x2 %0, %1, %2;" : "=l"(d) : "l"(a), "l"(b));
    return d;
}

// ---- one-shot pyramid builder ----------------------------------------------
__global__ void __launch_bounds__(256)
pool_all_kernel(const float* __restrict__ A, const float* __restrict__ B) {
    const int bid = blockIdx.x;
    const int tx = bid & 15;
    const int ty = (bid >> 4) & 15;
    const int z  = bid >> 8;

    __shared__ float hA[32][17], hB[32][17];
    __shared__ float l1A[16][17], l1B[16][17];
    __shared__ float l2A[8][9],  l2B[8][9];
    __shared__ float l3A[4][5],  l3B[4][5];

    const int t = threadIdx.x;

    // block 0 zeroes the level accumulators (pool_all precedes ssim_all)
    if (bid == 0 && t < 10) g_acc[t] = 0.0;

    // load 32x32 tile (each thread one float4 per image), horizontal pairs
    {
        const int r  = t >> 3;
        const int c4 = t & 7;
        size_t src = (((size_t)z * 512) + ty * 32 + r) * 512 + tx * 32 + c4 * 4;
        float4 a = *(const float4*)(A + src);
        float4 b = *(const float4*)(B + src);
        hA[r][c4 * 2]     = a.x + a.y;
        hA[r][c4 * 2 + 1] = a.z + a.w;
        hB[r][c4 * 2]     = b.x + b.y;
        hB[r][c4 * 2 + 1] = b.z + b.w;
    }
    __syncthreads();

    // L1: 16x16
    {
        const int y = t >> 4, x = t & 15;
        float va = 0.25f * (hA[2 * y][x] + hA[2 * y + 1][x]);
        float vb = 0.25f * (hB[2 * y][x] + hB[2 * y + 1][x]);
        l1A[y][x] = va; l1B[y][x] = vb;
        size_t o = (((size_t)z * 256) + ty * 16 + y) * 256 + tx * 16 + x;
        g_p1[O1 + o] = va;
        g_p2[O1 + o] = vb;
    }
    __syncthreads();

    // L2: 8x8
    if (t < 64) {
        const int y = t >> 3, x = t & 7;
        float va = 0.25f * (l1A[2*y][2*x] + l1A[2*y][2*x+1] +
                            l1A[2*y+1][2*x] + l1A[2*y+1][2*x+1]);
        float vb = 0.25f * (l1B[2*y][2*x] + l1B[2*y][2*x+1] +
                            l1B[2*y+1][2*x] + l1B[2*y+1][2*x+1]);
        l2A[y][x] = va; l2B[y][x] = vb;
        size_t o = (((size_t)z * 128) + ty * 8 + y) * 128 + tx * 8 + x;
        g_p1[O2 + o] = va;
        g_p2[O2 + o] = vb;
    }
    __syncthreads();

    // L3: 4x4
    if (t < 16) {
        const int y = t >> 2, x = t & 3;
        float va = 0.25f * (l2A[2*y][2*x] + l2A[2*y][2*x+1] +
                            l2A[2*y+1][2*x] + l2A[2*y+1][2*x+1]);
        float vb = 0.25f * (l2B[2*y][2*x] + l2B[2*y][2*x+1] +
                            l2B[2*y+1][2*x] + l2B[2*y+1][2*x+1]);
        l3A[y][x] = va; l3B[y][x] = vb;
        size_t o = (((size_t)z * 64) + ty * 4 + y) * 64 + tx * 4 + x;
        g_p1[O3 + o] = va;
        g_p2[O3 + o] = vb;
    }
    __syncthreads();

    // L4: 2x2
    if (t < 4) {
        const int y = t >> 1, x = t & 1;
        float va = 0.25f * (l3A[2*y][2*x] + l3A[2*y][2*x+1] +
                            l3A[2*y+1][2*x] + l3A[2*y+1][2*x+1]);
        float vb = 0.25f * (l3B[2*y][2*x] + l3B[2*y][2*x+1] +
                            l3B[2*y+1][2*x] + l3B[2*y+1][2*x+1]);
        size_t o = (((size_t)z * 32) + ty * 2 + y) * 32 + tx * 2 + x;
        g_p1[O4 + o] = va;
        g_p2[O4 + o] = vb;
    }
}

__global__ void __launch_bounds__(OC, 6)
ssim_all_kernel(const float* __restrict__ img1, const float* __restrict__ img2) {
    __shared__ float2 sUW[IR * ICW];   // packed (a+b, a-b)

    // ---- decode linear block id -> (level, bx, by, z) ----
    int lid = blockIdx.x;
    int level, H, GX, GY;
    if (lid < NB0)                    { level = 0; H = 512; GX = 4; GY = 21; }
    else if ((lid -= NB0) < NB1)      { level = 1; H = 256; GX = 2; GY = 11; }
    else if ((lid -= NB1) < NB2)      { level = 2; H = 128; GX = 1; GY = 5;  }
    else if ((lid -= NB2) < NB3)      { level = 3; H = 64;  GX = 1; GY = 3;  }
    else { lid -= NB3;                  level = 4; H = 32;  GX = 1; GY = 1;  }
    const int bx = lid % GX;
    const int t1 = lid / GX;
    const int by = t1 % GY;
    const int z  = t1 / GY;

    const float* baseA;
    const float* baseB;
    if (level == 0) { baseA = img1; baseB = img2; }
    else {
        unsigned off = (level == 1) ? O1 : (level == 2) ? O2
                     : (level == 3) ? O3 : O4;
        baseA = g_p1 + off;
        baseB = g_p2 + off;
    }

    const int tid = threadIdx.x;
    const int rowBase = by * ORR;
    const int colBase = bx * OC;
    const int W = H;
    const size_t zoff = (size_t)z * H * W;
    const float* __restrict__ Ap = baseA + zoff;
    const float* __restrict__ Bp = baseB + zoff;

    // ---- division-free tile load: row loop, strength-reduced offsets ----
    {
        const int gc0 = colBase + tid;
        const int gc1 = colBase + OC + tid;          // halo column (tid<10)
        const bool c0ok = gc0 < W;
        const bool c1ok = (tid < ICW - OC) && (gc1 < W);
        size_t o0 = (size_t)rowBase * W + gc0;
        size_t o1 = (size_t)rowBase * W + gc1;
        #pragma unroll
        for (int r = 0; r < IR; r++) {
            const bool rok = (rowBase + r) < H;
            float u0 = 0.f, w0 = 0.f;
            if (rok && c0ok) {
                float a = __ldg(Ap + o0);
                float b = __ldg(Bp + o0);
                u0 = a + b; w0 = a - b;
            }
            sUW[r * ICW + tid] = make_float2(u0, w0);
            if (tid < ICW - OC) {
                float u1 = 0.f, w1 = 0.f;
                if (rok && c1ok) {
                    float a = __ldg(Ap + o1);
                    float b = __ldg(Bp + o1);
                    u1 = a + b; w1 = a - b;
                }
                sUW[r * ICW + OC + tid] = make_float2(u1, w1);
            }
            o0 += W;
            o1 += W;
        }
    }
    __syncthreads();

    const int oc = colBase + tid;
    const bool col_ok = oc < (W - 10);

    // 6 distinct packed taps (symmetry)
    ull Gp[6];
    Gp[0] = pk2(G0, G0); Gp[1] = pk2(G1, G1); Gp[2] = pk2(G2, G2);
    Gp[3] = pk2(G3, G3); Gp[4] = pk2(G4, G4); Gp[5] = pk2(G5, G5);

    // two packed register rings: conv(u,w) and conv(u^2,w^2)
    ull rUW[11], rSQ[11];
    float accS = 0.f, accC = 0.f;

    #pragma unroll
    for (int r = 0; r < IR; r++) {
        // ---- horizontal pass: 11x (LDS.64 + mul2 + 2x fma2) ----
        ull sUWa = 0ull, sSQa = 0ull;
        const ull* __restrict__ rowp =
            reinterpret_cast<const ull*>(sUW) + r * ICW + tid;
        #pragma unroll
        for (int k = 0; k < 11; k++) {
            ull vp = rowp[k];                         // LDS.64 (u,w)
            ull g  = Gp[k < 6 ? k : 10 - k];
            sUWa = fma2(vp, g, sUWa);
            sSQa = fma2(mul2(vp, vp), g, sSQa);
        }
        const int slot = r % 11;                      // compile-time
        rUW[slot] = sUWa;
        rSQ[slot] = sSQa;

        // ---- vertical pass: 11x (2x fma2) ----
        if (r >= 10) {
            ull mUW = 0ull, mSQ = 0ull;
            #pragma unroll
            for (int j = 0; j < 11; j++) {
                const int sl = (r - 10 + j) % 11;     // compile-time
                ull g = Gp[j < 6 ? j : 10 - j];
                mUW = fma2(rUW[sl], g, mUW);
                mSQ = fma2(rSQ[sl], g, mSQ);
            }
            int gr = rowBase + r;
            if (col_ok && gr < H) {
                float cU2, cW2, p, q;
                upk2(mSQ, cU2, cW2);
                ull pq = mul2(mUW, mUW);              // (cu^2, cw^2)
                upk2(pq, p, q);
                float n1 = 0.5f * (p - q) + C1V;
                float d1 = 0.5f * (p + q) + C1V;
                float v1 = 0.5f * ((cU2 - cW2) - (p - q)) + C2V;
                float v2 = 0.5f * ((cU2 + cW2) - (p + q)) + C2V;
                float cs = __fdividef(v1, v2);
                float ssim = cs * __fdividef(n1, d1);
                accS += ssim;
                accC += cs;
            }
        }
    }

    // ---- block reduction ----
    #pragma unroll
    for (int off = 16; off > 0; off >>= 1) {
        accS += __shfl_down_sync(0xFFFFFFFFu, accS, off);
        accC += __shfl_down_sync(0xFFFFFFFFu, accC, off);
    }
    __shared__ float wS[OC / 32], wC[OC / 32];
    const int warp = tid >> 5, lane = tid & 31;
    if (lane == 0) { wS[warp] = accS; wC[warp] = accC; }
    __syncthreads();
    if (tid == 0) {
        float bs = 0.f, bc = 0.f;
        #pragma unroll
        for (int wi = 0; wi < OC / 32; wi++) { bs += wS[wi]; bc += wC[wi]; }
        atomicAdd(&g_acc[2 * level],     (double)bs);
        atomicAdd(&g_acc[2 * level + 1], (double)bc);
    }
}

// fp32 combine via log2/exp2 (values in (0.9, 1.0]; rel. err ~1e-7 << 1e-3)
__global__ void final_kernel(float* __restrict__ out) {
    const float Hl[5] = {502.f, 246.f, 118.f, 54.f, 22.f};
    const float Wt[5] = {0.0448f, 0.2856f, 0.3001f, 0.2363f, 0.1333f};
    float lsum = 0.f;
    #pragma unroll
    for (int l = 0; l < 5; l++) {
        float inv_cnt = 1.f / (48.f * Hl[l] * Hl[l]);
        float ms = ((float)g_acc[2 * l]     * inv_cnt + 1.f) * 0.5f;
        float mc = ((float)g_acc[2 * l + 1] * inv_cnt + 1.f) * 0.5f;
        // prod(pow1[:-1] * pow2[-1]): mcs^{w_l} for l<4, mssim4^{4*w_4}
        float x = (l < 4) ? mc : ms;
        float w = (l < 4) ? Wt[l] : 4.f * Wt[4];
        lsum += w * log2f(x);
    }
    out[0] = exp2f(lsum);
}

extern "C" void kernel_launch(void* const* d_in, const int* in_sizes, int n_in,
                              void* d_out, int out_size) {
    const float* img1 = (const float*)d_in[0];
    const float* img2 = (const float*)d_in[1];
    float* out = (float*)d_out;

    // one launch builds the whole pyramid (and zeroes accumulators),
    // then one wave-packed ssim launch, then a tiny fp32 combine.
    pool_all_kernel<<<48 * 16 * 16, 256>>>(img1, img2);

    ssim_all_kernel<<<NBALL, OC>>>(img1, img2);

    final_kernel<<<1, 1>>>(out);
}

// round 15
// speedup vs baseline: 1.7026x; 1.7026x over previous
#include <cuda_runtime.h>
#include <cuda_bf16.h>
#include <math.h>

// ===========================================================================
// MS-SSIM 16x3x512x512 fp32, 5 levels.  (round-12 structure; pool_all now
// computes L1 directly in registers, skipping the 32x32 smem staging)
// pool_all_kernel: ONE launch builds the whole 4-level pyramid (256 thr/blk);
//   block 0 zeroes the g_acc accumulators.
// ssim_all_kernel: ONE launch, all 5 levels (5520 blocks), 6 CTAs/SM.
//   Core: sum/diff transform, packed f32x2 FMA. (unchanged from round 12)
// final_kernel: fp32 log2/exp2 combine.
// ===========================================================================

#define OC  128           // output columns per block (== threads)
#define ORR 24            // output rows per block
#define IR  (ORR + 10)    // 34 input rows
#define ICW (OC + 10)     // 138 input cols

// Gaussian taps, sigma=1.5, ws=11
#define G0 0.00102838f
#define G1 0.00759876f
#define G2 0.03600077f
#define G3 0.10936069f
#define G4 0.21300553f
#define G5 0.26601172f

#define C1V 1.0e-4f
#define C2V 9.0e-4f

// Scratch for pooled pyramids
#define S1 (48u * 256u * 256u)
#define S2 (48u * 128u * 128u)
#define S3 (48u * 64u  * 64u)
#define S4 (48u * 32u  * 32u)
#define O1 0u
#define O2 (S1)
#define O3 (S1 + S2)
#define O4 (S1 + S2 + S3)
#define TOT (S1 + S2 + S3 + S4)

// per-level block counts (ORR=24: GY = ceil((H-10)/24))
#define NB0 4032   // 4 x 21 x 48   (H=512)
#define NB1 1056   // 2 x 11 x 48   (H=256)
#define NB2 240    // 1 x  5 x 48   (H=128)
#define NB3 144    // 1 x  3 x 48   (H=64)
#define NB4 48     // 1 x  1 x 48   (H=32)
#define NBALL (NB0 + NB1 + NB2 + NB3 + NB4)   // 5520

__device__ float g_p1[TOT];
__device__ float g_p2[TOT];
__device__ double g_acc[10];

// ---- f32x2 packed helpers -------------------------------------------------
typedef unsigned long long ull;
__device__ __forceinline__ ull pk2(float lo, float hi) {
    ull r;
    asm("mov.b64 %0, {%1, %2};" : "=l"(r) : "f"(lo), "f"(hi));
    return r;
}
__device__ __forceinline__ void upk2(ull v, float& lo, float& hi) {
    asm("mov.b64 {%0, %1}, %2;" : "=f"(lo), "=f"(hi) : "l"(v));
}
__device__ __forceinline__ ull fma2(ull a, ull b, ull c) {
    ull d;
    asm("fma.rn.f32x2 %0, %1, %2, %3;" : "=l"(d) : "l"(a), "l"(b), "l"(c));
    return d;
}
__device__ __forceinline__ ull mul2(ull a, ull b) {
    ull d;
    asm("mul.rn.f32x2 %0, %1, %2;" : "=l"(d) : "l"(a), "l"(b));
    return d;
}

// ---- one-shot pyramid builder ----------------------------------------------
// 256 threads; each thread computes one L1 (16x16) output per image directly
// from 4x LDG.64 (no 32x32 smem staging), then hierarchical L2..L4 in smem.
__global__ void __launch_bounds__(256)
pool_all_kernel(const float* __restrict__ A, const float* __restrict__ B) {
    const int bid = blockIdx.x;
    const int tx = bid & 15;
    const int ty = (bid >> 4) & 15;
    const int z  = bid >> 8;

    __shared__ float l1A[16][17], l1B[16][17];
    __shared__ float l2A[8][9],  l2B[8][9];
    __shared__ float l3A[4][5],  l3B[4][5];

    const int t = threadIdx.x;

    // block 0 zeroes the level accumulators (pool_all precedes ssim_all)
    if (bid == 0 && t < 10) g_acc[t] = 0.0;

    // L1: 16x16 — one output per thread per image, straight from gmem
    {
        const int y = t >> 4, x = t & 15;
        size_t src = (((size_t)z * 512) + ty * 32 + 2 * y) * 512
                   + tx * 32 + 2 * x;
        float2 a0 = *(const float2*)(A + src);
        float2 a1 = *(const float2*)(A + src + 512);
        float2 b0 = *(const float2*)(B + src);
        float2 b1 = *(const float2*)(B + src + 512);
        float va = 0.25f * ((a0.x + a0.y) + (a1.x + a1.y));
        float vb = 0.25f * ((b0.x + b0.y) + (b1.x + b1.y));
        l1A[y][x] = va; l1B[y][x] = vb;
        size_t o = (((size_t)z * 256) + ty * 16 + y) * 256 + tx * 16 + x;
        g_p1[O1 + o] = va;
        g_p2[O1 + o] = vb;
    }
    __syncthreads();

    // L2: 8x8
    if (t < 64) {
        const int y = t >> 3, x = t & 7;
        float va = 0.25f * (l1A[2*y][2*x] + l1A[2*y][2*x+1] +
                            l1A[2*y+1][2*x] + l1A[2*y+1][2*x+1]);
        float vb = 0.25f * (l1B[2*y][2*x] + l1B[2*y][2*x+1] +
                            l1B[2*y+1][2*x] + l1B[2*y+1][2*x+1]);
        l2A[y][x] = va; l2B[y][x] = vb;
        size_t o = (((size_t)z * 128) + ty * 8 + y) * 128 + tx * 8 + x;
        g_p1[O2 + o] = va;
        g_p2[O2 + o] = vb;
    }
    __syncthreads();

    // L3: 4x4
    if (t < 16) {
        const int y = t >> 2, x = t & 3;
        float va = 0.25f * (l2A[2*y][2*x] + l2A[2*y][2*x+1] +
                            l2A[2*y+1][2*x] + l2A[2*y+1][2*x+1]);
        float vb = 0.25f * (l2B[2*y][2*x] + l2B[2*y][2*x+1] +
                            l2B[2*y+1][2*x] + l2B[2*y+1][2*x+1]);
        l3A[y][x] = va; l3B[y][x] = vb;
        size_t o = (((size_t)z * 64) + ty * 4 + y) * 64 + tx * 4 + x;
        g_p1[O3 + o] = va;
        g_p2[O3 + o] = vb;
    }
    __syncthreads();

    // L4: 2x2
    if (t < 4) {
        const int y = t >> 1, x = t & 1;
        float va = 0.25f * (l3A[2*y][2*x] + l3A[2*y][2*x+1] +
                            l3A[2*y+1][2*x] + l3A[2*y+1][2*x+1]);
        float vb = 0.25f * (l3B[2*y][2*x] + l3B[2*y][2*x+1] +
                            l3B[2*y+1][2*x] + l3B[2*y+1][2*x+1]);
        size_t o = (((size_t)z * 32) + ty * 2 + y) * 32 + tx * 2 + x;
        g_p1[O4 + o] = va;
        g_p2[O4 + o] = vb;
    }
}

__global__ void __launch_bounds__(OC, 6)
ssim_all_kernel(const float* __restrict__ img1, const float* __restrict__ img2) {
    __shared__ float2 sUW[IR * ICW];   // packed (a+b, a-b)

    // ---- decode linear block id -> (level, bx, by, z) ----
    int lid = blockIdx.x;
    int level, H, GX, GY;
    if (lid < NB0)                    { level = 0; H = 512; GX = 4; GY = 21; }
    else if ((lid -= NB0) < NB1)      { level = 1; H = 256; GX = 2; GY = 11; }
    else if ((lid -= NB1) < NB2)      { level = 2; H = 128; GX = 1; GY = 5;  }
    else if ((lid -= NB2) < NB3)      { level = 3; H = 64;  GX = 1; GY = 3;  }
    else { lid -= NB3;                  level = 4; H = 32;  GX = 1; GY = 1;  }
    const int bx = lid % GX;
    const int t1 = lid / GX;
    const int by = t1 % GY;
    const int z  = t1 / GY;

    const float* baseA;
    const float* baseB;
    if (level == 0) { baseA = img1; baseB = img2; }
    else {
        unsigned off = (level == 1) ? O1 : (level == 2) ? O2
                     : (level == 3) ? O3 : O4;
        baseA = g_p1 + off;
        baseB = g_p2 + off;
    }

    const int tid = threadIdx.x;
    const int rowBase = by * ORR;
    const int colBase = bx * OC;
    const int W = H;
    const size_t zoff = (size_t)z * H * W;
    const float* __restrict__ Ap = baseA + zoff;
    const float* __restrict__ Bp = baseB + zoff;

    // ---- load tile as (u,w) (zero-clamped halo; masked outputs) ----
    for (int i = tid; i < IR * ICW; i += OC) {
        int r = i / ICW;
        int c = i - r * ICW;
        int gr = rowBase + r, gc = colBase + c;
        float u = 0.f, w = 0.f;
        if (gr < H && gc < W) {
            size_t o = (size_t)gr * W + gc;
            float a = __ldg(Ap + o);
            float b = __ldg(Bp + o);
            u = a + b;
            w = a - b;
        }
        sUW[i] = make_float2(u, w);
    }
    __syncthreads();

    const int oc = colBase + tid;
    const bool col_ok = oc < (W - 10);

    // 6 distinct packed taps (symmetry)
    ull Gp[6];
    Gp[0] = pk2(G0, G0); Gp[1] = pk2(G1, G1); Gp[2] = pk2(G2, G2);
    Gp[3] = pk2(G3, G3); Gp[4] = pk2(G4, G4); Gp[5] = pk2(G5, G5);

    // two packed register rings: conv(u,w) and conv(u^2,w^2)
    ull rUW[11], rSQ[11];
    float accS = 0.f, accC = 0.f;

    #pragma unroll
    for (int r = 0; r < IR; r++) {
        // ---- horizontal pass: 11x (LDS.64 + mul2 + 2x fma2) ----
        ull sUWa = 0ull, sSQa = 0ull;
        const ull* __restrict__ rowp =
            reinterpret_cast<const ull*>(sUW) + r * ICW + tid;
        #pragma unroll
        for (int k = 0; k < 11; k++) {
            ull vp = rowp[k];                         // LDS.64 (u,w)
            ull g  = Gp[k < 6 ? k : 10 - k];
            sUWa = fma2(vp, g, sUWa);
            sSQa = fma2(mul2(vp, vp), g, sSQa);
        }
        const int slot = r % 11;                      // compile-time
        rUW[slot] = sUWa;
        rSQ[slot] = sSQa;

        // ---- vertical pass: 11x (2x fma2) ----
        if (r >= 10) {
            ull mUW = 0ull, mSQ = 0ull;
            #pragma unroll
            for (int j = 0; j < 11; j++) {
                const int sl = (r - 10 + j) % 11;     // compile-time
                ull g = Gp[j < 6 ? j : 10 - j];
                mUW = fma2(rUW[sl], g, mUW);
                mSQ = fma2(rSQ[sl], g, mSQ);
            }
            int gr = rowBase + r;
            if (col_ok && gr < H) {
                float cU2, cW2, p, q;
                upk2(mSQ, cU2, cW2);
                ull pq = mul2(mUW, mUW);              // (cu^2, cw^2)
                upk2(pq, p, q);
                float n1 = 0.5f * (p - q) + C1V;
                float d1 = 0.5f * (p + q) + C1V;
                float v1 = 0.5f * ((cU2 - cW2) - (p - q)) + C2V;
                float v2 = 0.5f * ((cU2 + cW2) - (p + q)) + C2V;
                float cs = __fdividef(v1, v2);
                float ssim = cs * __fdividef(n1, d1);
                accS += ssim;
                accC += cs;
            }
        }
    }

    // ---- block reduction ----
    #pragma unroll
    for (int off = 16; off > 0; off >>= 1) {
        accS += __shfl_down_sync(0xFFFFFFFFu, accS, off);
        accC += __shfl_down_sync(0xFFFFFFFFu, accC, off);
    }
    __shared__ float wS[OC / 32], wC[OC / 32];
    const int warp = tid >> 5, lane = tid & 31;
    if (lane == 0) { wS[warp] = accS; wC[warp] = accC; }
    __syncthreads();
    if (tid == 0) {
        float bs = 0.f, bc = 0.f;
        #pragma unroll
        for (int wi = 0; wi < OC / 32; wi++) { bs += wS[wi]; bc += wC[wi]; }
        atomicAdd(&g_acc[2 * level],     (double)bs);
        atomicAdd(&g_acc[2 * level + 1], (double)bc);
    }
}

// fp32 combine via log2/exp2 (values in (0.9, 1.0]; rel. err ~1e-7 << 1e-3)
__global__ void final_kernel(float* __restrict__ out) {
    const float Hl[5] = {502.f, 246.f, 118.f, 54.f, 22.f};
    const float Wt[5] = {0.0448f, 0.2856f, 0.3001f, 0.2363f, 0.1333f};
    float lsum = 0.f;
    #pragma unroll
    for (int l = 0; l < 5; l++) {
        float inv_cnt = 1.f / (48.f * Hl[l] * Hl[l]);
        float ms = ((float)g_acc[2 * l]     * inv_cnt + 1.f) * 0.5f;
        float mc = ((float)g_acc[2 * l + 1] * inv_cnt + 1.f) * 0.5f;
        // prod(pow1[:-1] * pow2[-1]): mcs^{w_l} for l<4, mssim4^{4*w_4}
        float x = (l < 4) ? mc : ms;
        float w = (l < 4) ? Wt[l] : 4.f * Wt[4];
        lsum += w * log2f(x);
    }
    out[0] = exp2f(lsum);
}

extern "C" void kernel_launch(void* const* d_in, const int* in_sizes, int n_in,
                              void* d_out, int out_size) {
    const float* img1 = (const float*)d_in[0];
    const float* img2 = (const float*)d_in[1];
    float* out = (float*)d_out;

    // one launch builds the whole pyramid (and zeroes accumulators),
    // then one wave-packed ssim launch, then a tiny fp32 combine.
    pool_all_kernel<<<48 * 16 * 16, 256>>>(img1, img2);

    ssim_all_kernel<<<NBALL, OC>>>(img1, img2);

    final_kernel<<<1, 1>>>(out);
}

// round 16
// speedup vs baseline: 1.7571x; 1.0320x over previous
#include <cuda_runtime.h>
#include <cuda_bf16.h>
#include <math.h>

// ===========================================================================
// MS-SSIM 16x3x512x512 fp32, 5 levels.
// A: ssim level-0 (4032 blocks) with FUSED L1 pyramid production from the
//    already-loaded smem tile (kills pool's redundant 100MB image re-read).
// B: pool L2-4 from L1 (3072 blocks, 256 thr) — small.
// C: ssim levels 1-4 (1488 blocks).
// ssim core: sum/diff transform, packed f32x2 FMA (frozen since round 9).
// final: fp32 log2/exp2 combine.
// ===========================================================================

#define OC  128           // output columns per block (== threads)
#define ORR 24            // output rows per block
#define IR  (ORR + 10)    // 34 input rows
#define ICW (OC + 10)     // 138 input cols

// Gaussian taps, sigma=1.5, ws=11
#define G0 0.00102838f
#define G1 0.00759876f
#define G2 0.03600077f
#define G3 0.10936069f
#define G4 0.21300553f
#define G5 0.26601172f

#define C1V 1.0e-4f
#define C2V 9.0e-4f

// Scratch for pooled pyramids
#define S1 (48u * 256u * 256u)
#define S2 (48u * 128u * 128u)
#define S3 (48u * 64u  * 64u)
#define S4 (48u * 32u  * 32u)
#define O1 0u
#define O2 (S1)
#define O3 (S1 + S2)
#define O4 (S1 + S2 + S3)
#define TOT (S1 + S2 + S3 + S4)

// per-level ssim block counts (ORR=24: GY = ceil((H-10)/24))
#define NB0 4032   // 4 x 21 x 48   (H=512)
#define NB1 1056   // 2 x 11 x 48   (H=256)
#define NB2 240    // 1 x  5 x 48   (H=128)
#define NB3 144    // 1 x  3 x 48   (H=64)
#define NB4 48     // 1 x  1 x 48   (H=32)
#define NBC (NB1 + NB2 + NB3 + NB4)   // 1488

__device__ float g_p1[TOT];
__device__ float g_p2[TOT];
__device__ double g_acc[10];

// ---- f32x2 packed helpers -------------------------------------------------
typedef unsigned long long ull;
__device__ __forceinline__ ull pk2(float lo, float hi) {
    ull r;
    asm("mov.b64 %0, {%1, %2};" : "=l"(r) : "f"(lo), "f"(hi));
    return r;
}
__device__ __forceinline__ void upk2(ull v, float& lo, float& hi) {
    asm("mov.b64 {%0, %1}, %2;" : "=f"(lo), "=f"(hi) : "l"(v));
}
__device__ __forceinline__ ull fma2(ull a, ull b, ull c) {
    ull d;
    asm("fma.rn.f32x2 %0, %1, %2, %3;" : "=l"(d) : "l"(a), "l"(b), "l"(c));
    return d;
}
__device__ __forceinline__ ull mul2(ull a, ull b) {
    ull d;
    asm("mul.rn.f32x2 %0, %1, %2;" : "=l"(d) : "l"(a), "l"(b));
    return d;
}

// ---- ssim core (optionally emits L1 pooled outputs for level 0) ------------
template <bool POOL>
__device__ __forceinline__ void ssim_core(
    float2* sUW, const float* __restrict__ baseA,
    const float* __restrict__ baseB, int H, int bx, int by, int z, int level)
{
    const int tid = threadIdx.x;
    const int rowBase = by * ORR;
    const int colBase = bx * OC;
    const int W = H;
    const size_t zoff = (size_t)z * H * W;
    const float* __restrict__ Ap = baseA + zoff;
    const float* __restrict__ Bp = baseB + zoff;

    // load tile as (u,w) = (a+b, a-b); zero-clamped halo, masked outputs
    for (int i = tid; i < IR * ICW; i += OC) {
        int r = i / ICW;
        int c = i - r * ICW;
        int gr = rowBase + r, gc = colBase + c;
        float u = 0.f, w = 0.f;
        if (gr < H && gc < W) {
            size_t o = (size_t)gr * W + gc;
            float a = __ldg(Ap + o);
            float b = __ldg(Bp + o);
            u = a + b;
            w = a - b;
        }
        sUW[i] = make_float2(u, w);
    }
    __syncthreads();

    if (POOL) {
        // emit this block's disjoint slice of the L1 pyramid (2x2 avg-pool):
        // rows [rowBase, rowBase+24) per block; by==20 also covers [504,512).
        // a = (u+w)/2, b = (u-w)/2  ->  pooled: 0.125*(Su +/- Sw)
        const int PR = (by == 20) ? 16 : 12;
        const int n = 64 * PR;
        for (int i = tid; i < n; i += OC) {
            int y = i >> 6, x = i & 63;
            const float2* rp0 = &sUW[(2 * y) * ICW + 2 * x];
            const float2* rp1 = rp0 + ICW;
            float2 p00 = rp0[0], p01 = rp0[1];
            float2 p10 = rp1[0], p11 = rp1[1];
            float su = (p00.x + p01.x) + (p10.x + p11.x);
            float sw = (p00.y + p01.y) + (p10.y + p11.y);
            size_t o = (((size_t)z * 256) + 12 * by + y) * 256 + (bx << 6) + x;
            g_p1[O1 + o] = 0.125f * (su + sw);
            g_p2[O1 + o] = 0.125f * (su - sw);
        }
    }

    const int oc = colBase + tid;
    const bool col_ok = oc < (W - 10);

    ull Gp[6];
    Gp[0] = pk2(G0, G0); Gp[1] = pk2(G1, G1); Gp[2] = pk2(G2, G2);
    Gp[3] = pk2(G3, G3); Gp[4] = pk2(G4, G4); Gp[5] = pk2(G5, G5);

    ull rUW[11], rSQ[11];
    float accS = 0.f, accC = 0.f;

    #pragma unroll
    for (int r = 0; r < IR; r++) {
        // horizontal: 11x (LDS.64 + mul2 + 2x fma2)
        ull sUWa = 0ull, sSQa = 0ull;
        const ull* __restrict__ rowp =
            reinterpret_cast<const ull*>(sUW) + r * ICW + tid;
        #pragma unroll
        for (int k = 0; k < 11; k++) {
            ull vp = rowp[k];
            ull g  = Gp[k < 6 ? k : 10 - k];
            sUWa = fma2(vp, g, sUWa);
            sSQa = fma2(mul2(vp, vp), g, sSQa);
        }
        const int slot = r % 11;
        rUW[slot] = sUWa;
        rSQ[slot] = sSQa;

        // vertical: 11x (2x fma2)
        if (r >= 10) {
            ull mUW = 0ull, mSQ = 0ull;
            #pragma unroll
            for (int j = 0; j < 11; j++) {
                const int sl = (r - 10 + j) % 11;
                ull g = Gp[j < 6 ? j : 10 - j];
                mUW = fma2(rUW[sl], g, mUW);
                mSQ = fma2(rSQ[sl], g, mSQ);
            }
            int gr = rowBase + r;
            if (col_ok && gr < H) {
                float cU2, cW2, p, q;
                upk2(mSQ, cU2, cW2);
                ull pq = mul2(mUW, mUW);
                upk2(pq, p, q);
                float n1 = 0.5f * (p - q) + C1V;
                float d1 = 0.5f * (p + q) + C1V;
                float v1 = 0.5f * ((cU2 - cW2) - (p - q)) + C2V;
                float v2 = 0.5f * ((cU2 + cW2) - (p + q)) + C2V;
                float cs = __fdividef(v1, v2);
                float ssim = cs * __fdividef(n1, d1);
                accS += ssim;
                accC += cs;
            }
        }
    }

    // block reduction
    #pragma unroll
    for (int off = 16; off > 0; off >>= 1) {
        accS += __shfl_down_sync(0xFFFFFFFFu, accS, off);
        accC += __shfl_down_sync(0xFFFFFFFFu, accC, off);
    }
    __shared__ float wS[OC / 32], wC[OC / 32];
    const int warp = tid >> 5, lane = tid & 31;
    if (lane == 0) { wS[warp] = accS; wC[warp] = accC; }
    __syncthreads();
    if (tid == 0) {
        float bs = 0.f, bc = 0.f;
        #pragma unroll
        for (int wi = 0; wi < OC / 32; wi++) { bs += wS[wi]; bc += wC[wi]; }
        atomicAdd(&g_acc[2 * level],     (double)bs);
        atomicAdd(&g_acc[2 * level + 1], (double)bc);
    }
}

// ---- kernel A: ssim level 0 + fused L1 pool --------------------------------
__global__ void __launch_bounds__(OC, 6)
ssim0_kernel(const float* __restrict__ img1, const float* __restrict__ img2) {
    __shared__ float2 sUW[IR * ICW];
    const int lid = blockIdx.x;
    const int bx = lid & 3;
    const int t1 = lid >> 2;
    ssim_core<true>(sUW, img1, img2, 512, bx, t1 % 21, t1 / 21, 0);
}

// ---- kernel B: pool L2-4 from L1 (each block: 32x32 L1 region) -------------
__global__ void __launch_bounds__(256)
pool_l234_kernel() {
    const int bid = blockIdx.x;
    const int tx = bid & 7;
    const int ty = (bid >> 3) & 7;
    const int z  = bid >> 6;

    __shared__ float l2A[16][17], l2B[16][17];
    __shared__ float l3A[8][9],  l3B[8][9];

    const int t = threadIdx.x;

    // L2: 16x16 — one output per thread per image, straight from L1 gmem
    {
        const int y = t >> 4, x = t & 15;
        size_t src = (((size_t)z * 256) + ty * 32 + 2 * y) * 256
                   + tx * 32 + 2 * x;
        float2 a0 = *(const float2*)(g_p1 + O1 + src);
        float2 a1 = *(const float2*)(g_p1 + O1 + src + 256);
        float2 b0 = *(const float2*)(g_p2 + O1 + src);
        float2 b1 = *(const float2*)(g_p2 + O1 + src + 256);
        float va = 0.25f * ((a0.x + a0.y) + (a1.x + a1.y));
        float vb = 0.25f * ((b0.x + b0.y) + (b1.x + b1.y));
        l2A[y][x] = va; l2B[y][x] = vb;
        size_t o = (((size_t)z * 128) + ty * 16 + y) * 128 + tx * 16 + x;
        g_p1[O2 + o] = va;
        g_p2[O2 + o] = vb;
    }
    __syncthreads();

    // L3: 8x8
    if (t < 64) {
        const int y = t >> 3, x = t & 7;
        float va = 0.25f * (l2A[2*y][2*x] + l2A[2*y][2*x+1] +
                            l2A[2*y+1][2*x] + l2A[2*y+1][2*x+1]);
        float vb = 0.25f * (l2B[2*y][2*x] + l2B[2*y][2*x+1] +
                            l2B[2*y+1][2*x] + l2B[2*y+1][2*x+1]);
        l3A[y][x] = va; l3B[y][x] = vb;
        size_t o = (((size_t)z * 64) + ty * 8 + y) * 64 + tx * 8 + x;
        g_p1[O3 + o] = va;
        g_p2[O3 + o] = vb;
    }
    __syncthreads();

    // L4: 4x4
    if (t < 16) {
        const int y = t >> 2, x = t & 3;
        float va = 0.25f * (l3A[2*y][2*x] + l3A[2*y][2*x+1] +
                            l3A[2*y+1][2*x] + l3A[2*y+1][2*x+1]);
        float vb = 0.25f * (l3B[2*y][2*x] + l3B[2*y][2*x+1] +
                            l3B[2*y+1][2*x] + l3B[2*y+1][2*x+1]);
        size_t o = (((size_t)z * 32) + ty * 4 + y) * 32 + tx * 4 + x;
        g_p1[O4 + o] = va;
        g_p2[O4 + o] = vb;
    }
}

// ---- kernel C: ssim levels 1-4 ---------------------------------------------
__global__ void __launch_bounds__(OC, 6)
ssim14_kernel() {
    __shared__ float2 sUW[IR * ICW];
    int lid = blockIdx.x;
    int level, H, GX, GY;
    if (lid < NB1)                    { level = 1; H = 256; GX = 2; GY = 11; }
    else if ((lid -= NB1) < NB2)      { level = 2; H = 128; GX = 1; GY = 5;  }
    else if ((lid -= NB2) < NB3)      { level = 3; H = 64;  GX = 1; GY = 3;  }
    else { lid -= NB3;                  level = 4; H = 32;  GX = 1; GY = 1;  }
    const int bx = lid % GX;
    const int t1 = lid / GX;
    const int by = t1 % GY;
    const int z  = t1 / GY;
    const unsigned off = (level == 1) ? O1 : (level == 2) ? O2
                       : (level == 3) ? O3 : O4;
    ssim_core<false>(sUW, g_p1 + off, g_p2 + off, H, bx, by, z, level);
}

// fp32 combine via log2/exp2 (values in (0.9, 1.0]; rel. err ~1e-7 << 1e-3)
__global__ void final_kernel(float* __restrict__ out) {
    const float Hl[5] = {502.f, 246.f, 118.f, 54.f, 22.f};
    const float Wt[5] = {0.0448f, 0.2856f, 0.3001f, 0.2363f, 0.1333f};
    float lsum = 0.f;
    #pragma unroll
    for (int l = 0; l < 5; l++) {
        float inv_cnt = 1.f / (48.f * Hl[l] * Hl[l]);
        float ms = ((float)g_acc[2 * l]     * inv_cnt + 1.f) * 0.5f;
        float mc = ((float)g_acc[2 * l + 1] * inv_cnt + 1.f) * 0.5f;
        // prod(pow1[:-1] * pow2[-1]): mcs^{w_l} for l<4, mssim4^{4*w_4}
        float x = (l < 4) ? mc : ms;
        float w = (l < 4) ? Wt[l] : 4.f * Wt[4];
        lsum += w * log2f(x);
    }
    out[0] = exp2f(lsum);
}

extern "C" void kernel_launch(void* const* d_in, const int* in_sizes, int n_in,
                              void* d_out, int out_size) {
    const float* img1 = (const float*)d_in[0];
    const float* img2 = (const float*)d_in[1];
    float* out = (float*)d_out;

    double* acc;
    cudaGetSymbolAddress((void**)&acc, g_acc);
    cudaMemsetAsync(acc, 0, 10 * sizeof(double));

    ssim0_kernel<<<NB0, OC>>>(img1, img2);    // ssim L0 + fused L1 pool
    pool_l234_kernel<<<48 * 64, 256>>>();     // L2-4 from L1 (small)
    ssim14_kernel<<<NBC, OC>>>();             // ssim L1-4
    final_kernel<<<1, 1>>>(out);
}

// round 17
// speedup vs baseline: 1.7688x; 1.0067x over previous
#include <cuda_runtime.h>
#include <cuda_bf16.h>
#include <math.h>

// ===========================================================================
// MS-SSIM 16x3x512x512 fp32, 5 levels.  3 launches total.
// A: ssim level-0 (4032 blocks) with FUSED L1 pyramid production.
// B: pool L2-4 from L1 (3072 blocks, 256 thr).
// C: ssim levels 1-4 (1488 blocks) + last-block final combine (ticket
//    pattern; g_acc/g_ticket reset after read for graph-replay determinism).
// ssim core: sum/diff transform, packed f32x2 FMA (frozen since round 9).
// ===========================================================================

#define OC  128           // output columns per block (== threads)
#define ORR 24            // output rows per block
#define IR  (ORR + 10)    // 34 input rows
#define ICW (OC + 10)     // 138 input cols

// Gaussian taps, sigma=1.5, ws=11
#define G0 0.00102838f
#define G1 0.00759876f
#define G2 0.03600077f
#define G3 0.10936069f
#define G4 0.21300553f
#define G5 0.26601172f

#define C1V 1.0e-4f
#define C2V 9.0e-4f

// Scratch for pooled pyramids
#define S1 (48u * 256u * 256u)
#define S2 (48u * 128u * 128u)
#define S3 (48u * 64u  * 64u)
#define S4 (48u * 32u  * 32u)
#define O1 0u
#define O2 (S1)
#define O3 (S1 + S2)
#define O4 (S1 + S2 + S3)
#define TOT (S1 + S2 + S3 + S4)

// per-level ssim block counts (ORR=24: GY = ceil((H-10)/24))
#define NB0 4032   // 4 x 21 x 48   (H=512)
#define NB1 1056   // 2 x 11 x 48   (H=256)
#define NB2 240    // 1 x  5 x 48   (H=128)
#define NB3 144    // 1 x  3 x 48   (H=64)
#define NB4 48     // 1 x  1 x 48   (H=32)
#define NBC (NB1 + NB2 + NB3 + NB4)   // 1488

__device__ float g_p1[TOT];
__device__ float g_p2[TOT];
__device__ double g_acc[10];          // statically zero-initialized
__device__ unsigned g_ticket;         // statically zero-initialized

// ---- f32x2 packed helpers -------------------------------------------------
typedef unsigned long long ull;
__device__ __forceinline__ ull pk2(float lo, float hi) {
    ull r;
    asm("mov.b64 %0, {%1, %2};" : "=l"(r) : "f"(lo), "f"(hi));
    return r;
}
__device__ __forceinline__ void upk2(ull v, float& lo, float& hi) {
    asm("mov.b64 {%0, %1}, %2;" : "=f"(lo), "=f"(hi) : "l"(v));
}
__device__ __forceinline__ ull fma2(ull a, ull b, ull c) {
    ull d;
    asm("fma.rn.f32x2 %0, %1, %2, %3;" : "=l"(d) : "l"(a), "l"(b), "l"(c));
    return d;
}
__device__ __forceinline__ ull mul2(ull a, ull b) {
    ull d;
    asm("mul.rn.f32x2 %0, %1, %2;" : "=l"(d) : "l"(a), "l"(b));
    return d;
}

// ---- ssim core (optionally emits L1 pooled outputs for level 0) ------------
template <bool POOL>
__device__ __forceinline__ void ssim_core(
    float2* sUW, const float* __restrict__ baseA,
    const float* __restrict__ baseB, int H, int bx, int by, int z, int level)
{
    const int tid = threadIdx.x;
    const int rowBase = by * ORR;
    const int colBase = bx * OC;
    const int W = H;
    const size_t zoff = (size_t)z * H * W;
    const float* __restrict__ Ap = baseA + zoff;
    const float* __restrict__ Bp = baseB + zoff;

    // load tile as (u,w) = (a+b, a-b); zero-clamped halo, masked outputs
    for (int i = tid; i < IR * ICW; i += OC) {
        int r = i / ICW;
        int c = i - r * ICW;
        int gr = rowBase + r, gc = colBase + c;
        float u = 0.f, w = 0.f;
        if (gr < H && gc < W) {
            size_t o = (size_t)gr * W + gc;
            float a = __ldg(Ap + o);
            float b = __ldg(Bp + o);
            u = a + b;
            w = a - b;
        }
        sUW[i] = make_float2(u, w);
    }
    __syncthreads();

    if (POOL) {
        // emit this block's disjoint slice of the L1 pyramid (2x2 avg-pool):
        // rows [rowBase, rowBase+24); by==20 also covers [504,512).
        // a = (u+w)/2, b = (u-w)/2  ->  pooled: 0.125*(Su +/- Sw)
        const int PR = (by == 20) ? 16 : 12;
        const int n = 64 * PR;
        for (int i = tid; i < n; i += OC) {
            int y = i >> 6, x = i & 63;
            const float2* rp0 = &sUW[(2 * y) * ICW + 2 * x];
            const float2* rp1 = rp0 + ICW;
            float2 p00 = rp0[0], p01 = rp0[1];
            float2 p10 = rp1[0], p11 = rp1[1];
            float su = (p00.x + p01.x) + (p10.x + p11.x);
            float sw = (p00.y + p01.y) + (p10.y + p11.y);
            size_t o = (((size_t)z * 256) + 12 * by + y) * 256 + (bx << 6) + x;
            g_p1[O1 + o] = 0.125f * (su + sw);
            g_p2[O1 + o] = 0.125f * (su - sw);
        }
    }

    const int oc = colBase + tid;
    const bool col_ok = oc < (W - 10);

    ull Gp[6];
    Gp[0] = pk2(G0, G0); Gp[1] = pk2(G1, G1); Gp[2] = pk2(G2, G2);
    Gp[3] = pk2(G3, G3); Gp[4] = pk2(G4, G4); Gp[5] = pk2(G5, G5);

    ull rUW[11], rSQ[11];
    float accS = 0.f, accC = 0.f;

    #pragma unroll
    for (int r = 0; r < IR; r++) {
        // horizontal: 11x (LDS.64 + mul2 + 2x fma2)
        ull sUWa = 0ull, sSQa = 0ull;
        const ull* __restrict__ rowp =
            reinterpret_cast<const ull*>(sUW) + r * ICW + tid;
        #pragma unroll
        for (int k = 0; k < 11; k++) {
            ull vp = rowp[k];
            ull g  = Gp[k < 6 ? k : 10 - k];
            sUWa = fma2(vp, g, sUWa);
            sSQa = fma2(mul2(vp, vp), g, sSQa);
        }
        const int slot = r % 11;
        rUW[slot] = sUWa;
        rSQ[slot] = sSQa;

        // vertical: 11x (2x fma2)
        if (r >= 10) {
            ull mUW = 0ull, mSQ = 0ull;
            #pragma unroll
            for (int j = 0; j < 11; j++) {
                const int sl = (r - 10 + j) % 11;
                ull g = Gp[j < 6 ? j : 10 - j];
                mUW = fma2(rUW[sl], g, mUW);
                mSQ = fma2(rSQ[sl], g, mSQ);
            }
            int gr = rowBase + r;
            if (col_ok && gr < H) {
                float cU2, cW2, p, q;
                upk2(mSQ, cU2, cW2);
                ull pq = mul2(mUW, mUW);
                upk2(pq, p, q);
                float n1 = 0.5f * (p - q) + C1V;
                float d1 = 0.5f * (p + q) + C1V;
                float v1 = 0.5f * ((cU2 - cW2) - (p - q)) + C2V;
                float v2 = 0.5f * ((cU2 + cW2) - (p + q)) + C2V;
                float cs = __fdividef(v1, v2);
                float ssim = cs * __fdividef(n1, d1);
                accS += ssim;
                accC += cs;
            }
        }
    }

    // block reduction
    #pragma unroll
    for (int off = 16; off > 0; off >>= 1) {
        accS += __shfl_down_sync(0xFFFFFFFFu, accS, off);
        accC += __shfl_down_sync(0xFFFFFFFFu, accC, off);
    }
    __shared__ float wS[OC / 32], wC[OC / 32];
    const int warp = tid >> 5, lane = tid & 31;
    if (lane == 0) { wS[warp] = accS; wC[warp] = accC; }
    __syncthreads();
    if (tid == 0) {
        float bs = 0.f, bc = 0.f;
        #pragma unroll
        for (int wi = 0; wi < OC / 32; wi++) { bs += wS[wi]; bc += wC[wi]; }
        atomicAdd(&g_acc[2 * level],     (double)bs);
        atomicAdd(&g_acc[2 * level + 1], (double)bc);
    }
}

// ---- kernel A: ssim level 0 + fused L1 pool --------------------------------
__global__ void __launch_bounds__(OC, 6)
ssim0_kernel(const float* __restrict__ img1, const float* __restrict__ img2) {
    __shared__ float2 sUW[IR * ICW];
    const int lid = blockIdx.x;
    const int bx = lid & 3;
    const int t1 = lid >> 2;
    ssim_core<true>(sUW, img1, img2, 512, bx, t1 % 21, t1 / 21, 0);
}

// ---- kernel B: pool L2-4 from L1 (each block: 32x32 L1 region) -------------
__global__ void __launch_bounds__(256)
pool_l234_kernel() {
    const int bid = blockIdx.x;
    const int tx = bid & 7;
    const int ty = (bid >> 3) & 7;
    const int z  = bid >> 6;

    __shared__ float l2A[16][17], l2B[16][17];
    __shared__ float l3A[8][9],  l3B[8][9];

    const int t = threadIdx.x;

    // L2: 16x16 — one output per thread per image, straight from L1 gmem
    {
        const int y = t >> 4, x = t & 15;
        size_t src = (((size_t)z * 256) + ty * 32 + 2 * y) * 256
                   + tx * 32 + 2 * x;
        float2 a0 = *(const float2*)(g_p1 + O1 + src);
        float2 a1 = *(const float2*)(g_p1 + O1 + src + 256);
        float2 b0 = *(const float2*)(g_p2 + O1 + src);
        float2 b1 = *(const float2*)(g_p2 + O1 + src + 256);
        float va = 0.25f * ((a0.x + a0.y) + (a1.x + a1.y));
        float vb = 0.25f * ((b0.x + b0.y) + (b1.x + b1.y));
        l2A[y][x] = va; l2B[y][x] = vb;
        size_t o = (((size_t)z * 128) + ty * 16 + y) * 128 + tx * 16 + x;
        g_p1[O2 + o] = va;
        g_p2[O2 + o] = vb;
    }
    __syncthreads();

    // L3: 8x8
    if (t < 64) {
        const int y = t >> 3, x = t & 7;
        float va = 0.25f * (l2A[2*y][2*x] + l2A[2*y][2*x+1] +
                            l2A[2*y+1][2*x] + l2A[2*y+1][2*x+1]);
        float vb = 0.25f * (l2B[2*y][2*x] + l2B[2*y][2*x+1] +
                            l2B[2*y+1][2*x] + l2B[2*y+1][2*x+1]);
        l3A[y][x] = va; l3B[y][x] = vb;
        size_t o = (((size_t)z * 64) + ty * 8 + y) * 64 + tx * 8 + x;
        g_p1[O3 + o] = va;
        g_p2[O3 + o] = vb;
    }
    __syncthreads();

    // L4: 4x4
    if (t < 16) {
        const int y = t >> 2, x = t & 3;
        float va = 0.25f * (l3A[2*y][2*x] + l3A[2*y][2*x+1] +
                            l3A[2*y+1][2*x] + l3A[2*y+1][2*x+1]);
        float vb = 0.25f * (l3B[2*y][2*x] + l3B[2*y][2*x+1] +
                            l3B[2*y+1][2*x] + l3B[2*y+1][2*x+1]);
        size_t o = (((size_t)z * 32) + ty * 4 + y) * 32 + tx * 4 + x;
        g_p1[O4 + o] = va;
        g_p2[O4 + o] = vb;
    }
}

// ---- kernel C: ssim levels 1-4 + last-block final combine ------------------
__global__ void __launch_bounds__(OC, 6)
ssim14_kernel(float* __restrict__ out) {
    __shared__ float2 sUW[IR * ICW];
    int lid = blockIdx.x;
    int level, H, GX, GY;
    if (lid < NB1)                    { level = 1; H = 256; GX = 2; GY = 11; }
    else if ((lid -= NB1) < NB2)      { level = 2; H = 128; GX = 1; GY = 5;  }
    else if ((lid -= NB2) < NB3)      { level = 3; H = 64;  GX = 1; GY = 3;  }
    else { lid -= NB3;                  level = 4; H = 32;  GX = 1; GY = 1;  }
    const int bx = lid % GX;
    const int t1 = lid / GX;
    const int by = t1 % GY;
    const int z  = t1 / GY;
    const unsigned off = (level == 1) ? O1 : (level == 2) ? O2
                       : (level == 3) ? O3 : O4;
    ssim_core<false>(sUW, g_p1 + off, g_p2 + off, H, bx, by, z, level);

    // ---- last block computes the final combine (ticket pattern) ----
    __shared__ bool isLast;
    if (threadIdx.x == 0) {
        __threadfence();
        unsigned n = atomicAdd(&g_ticket, 1u);
        isLast = (n == NBC - 1);
    }
    __syncthreads();
    if (isLast && threadIdx.x == 0) {
        __threadfence();
        const float Hl[5] = {502.f, 246.f, 118.f, 54.f, 22.f};
        const float Wt[5] = {0.0448f, 0.2856f, 0.3001f, 0.2363f, 0.1333f};
        float lsum = 0.f;
        #pragma unroll
        for (int l = 0; l < 5; l++) {
            float inv_cnt = 1.f / (48.f * Hl[l] * Hl[l]);
            float ms = ((float)g_acc[2 * l]     * inv_cnt + 1.f) * 0.5f;
            float mc = ((float)g_acc[2 * l + 1] * inv_cnt + 1.f) * 0.5f;
            // prod(pow1[:-1] * pow2[-1]): mcs^{w_l} for l<4, mssim4^{4*w_4}
            float x = (l < 4) ? mc : ms;
            float w = (l < 4) ? Wt[l] : 4.f * Wt[4];
            lsum += w * log2f(x);
        }
        out[0] = exp2f(lsum);
        // reset state for the next graph replay (deterministic start)
        #pragma unroll
        for (int i = 0; i < 10; i++) g_acc[i] = 0.0;
        g_ticket = 0u;
    }
}

extern "C" void kernel_launch(void* const* d_in, const int* in_sizes, int n_in,
                              void* d_out, int out_size) {
    const float* img1 = (const float*)d_in[0];
    const float* img2 = (const float*)d_in[1];
    float* out = (float*)d_out;

    ssim0_kernel<<<NB0, OC>>>(img1, img2);    // ssim L0 + fused L1 pool
    pool_l234_kernel<<<48 * 64, 256>>>();     // L2-4 from L1 (small)
    ssim14_kernel<<<NBC, OC>>>(out);          // ssim L1-4 + final combine
}